// round 16
// baseline (speedup 1.0000x reference)
#include <cuda_runtime.h>
#include <cuda_bf16.h>
#include <cuda_fp16.h>
#include <math.h>
#include <stdint.h>

// ----- problem constants (fixed shapes) -----
#define NN     10000
#define EE     30000
#define IN_DIM 1024
#define H1     4
#define C1     512
#define D1     2048          // H1*C1
#define H2     8
#define C2     460
#define D2     3680          // H2*C2
#define D2PAD  3712          // 29*128
#define E2TOT  40000         // EE + NN (self loops)

#define S1     8192          // packed L1 output row stride: [q|k|v|skip]
#define OFF_Q  0
#define OFF_K  2048
#define OFF_V  4096
#define OFF_H  6144
#define S2     7424          // packed L2 output row stride: [gl(3712)|gr(3712)]
#define N1TOT  8192
#define N2TOT  7424

// ----- scratch (device globals; no allocations allowed) -----
__device__ __half g_b1[NN * S1];      // q|k|v|skip packed (fp16)
__device__ __half g_b2[NN * S2];      // gl|gr packed (fp16)
__device__ float  g_ex1[EE * H1];     // CSR-ordered exp(alpha), layer 1
__device__ int    g_src[EE];
__device__ int    g_dst[EE];
__device__ float  g_bias1[N1TOT];
__device__ float  g_bias2[N2TOT];

// CSR by dst (shared by both layers; layer-2 self loops handled inline)
__device__ int    g_cnt[NN];
__device__ int    g_fill[NN];
__device__ int    g_rowptr[NN + 1];
__device__ int    g_csr_src[EE];

// fp16 operands (A single fp16, weights single fp16 K-major [Ntot, K])
__device__ __half g_xh[NN * IN_DIM];
__device__ __half g_hh[NN * D1];
__device__ __half g_wt1[4 * D1 * IN_DIM];
__device__ __half g_wt2[2 * D2PAD * D1];

// ===================== GEMM (mma.sync fp16, 128x256 tile, 512 thr,
//                       ldmatrix, 5-stage, single barrier / K-step) =======
#define SMSTRIDE_B 80
#define TILE_A     (128 * SMSTRIDE_B)    // 10240
#define TILE_BB    (256 * SMSTRIDE_B)    // 20480
#define STAGE_B    (TILE_A + TILE_BB)    // 30720
#define GNS        5
#define GEMM_SMEM  (GNS * STAGE_B)       // 153600 -> 1 CTA/SM, 16 warps

__device__ __forceinline__ uint32_t smem_u32(const void* p) {
    uint32_t a;
    asm("{ .reg .u64 t; cvta.to.shared.u64 t, %1; cvt.u32.u64 %0, t; }" : "=r"(a) : "l"(p));
    return a;
}

__device__ __forceinline__ void mma16816(float* c, const uint32_t* a, const uint32_t* b)
{
    asm volatile(
        "mma.sync.aligned.m16n8k16.row.col.f32.f16.f16.f32 "
        "{%0,%1,%2,%3}, {%4,%5,%6,%7}, {%8,%9}, {%0,%1,%2,%3};"
        : "+f"(c[0]), "+f"(c[1]), "+f"(c[2]), "+f"(c[3])
        : "r"(a[0]), "r"(a[1]), "r"(a[2]), "r"(a[3]), "r"(b[0]), "r"(b[1]));
}

#define LDSM_X4(r0, r1, r2, r3, addr) \
    asm volatile("ldmatrix.sync.aligned.m8n8.x4.shared.b16 {%0,%1,%2,%3}, [%4];" \
                 : "=r"(r0), "=r"(r1), "=r"(r2), "=r"(r3) : "r"(addr))

__device__ __forceinline__ void store2(__half* p, float a, float b)
{ *(__half2*)p = __floats2half2_rn(a, b); }

// load 4 consecutive halves -> float4 (generic: works on global or smem)
__device__ __forceinline__ float4 ld_half4(const __half* p)
{
    uint2 u = *(const uint2*)p;
    __half2 h0 = *(__half2*)&u.x, h1 = *(__half2*)&u.y;
    float2 a = __half22float2(h0), b = __half22float2(h1);
    return make_float4(a.x, a.y, b.x, b.y);
}

__global__ __launch_bounds__(512, 1)
void gemm_mma(const __half* __restrict__ A, const __half* __restrict__ B,
              const float* __restrict__ bias, __half* __restrict__ C,
              int M, int NT, int K)
{
    extern __shared__ char smem[];
    const uint32_t sb = smem_u32(smem);
    const int tid  = threadIdx.x;
    const int wid  = tid >> 5, lane = tid & 31;
    const int row0 = blockIdx.y * 128;
    const int col0 = blockIdx.x * 256;
    const int KT   = K >> 5;

    const int aRow = tid >> 2, aChunk = (tid & 3) * 16;

    auto load_stage = [&](int slot, int kt) {
        {
            int grow = row0 + aRow;
            int sz = 16;
            if (grow >= M) { grow = M - 1; sz = 0; }
            const char* src = (const char*)A + (size_t)grow * ((size_t)K * 2)
                              + (size_t)kt * 64 + aChunk;
            uint32_t dst = sb + slot * STAGE_B + (uint32_t)aRow * SMSTRIDE_B + aChunk;
            asm volatile("cp.async.cg.shared.global [%0], [%1], 16, %2;"
                         :: "r"(dst), "l"(src), "r"(sz));
        }
#pragma unroll
        for (int r = 0; r < 2; r++) {
            int idx  = tid + r * 512;
            int brow = idx >> 2, bch = (idx & 3) * 16;
            const char* src = (const char*)B + (size_t)(col0 + brow) * ((size_t)K * 2)
                              + (size_t)kt * 64 + bch;
            uint32_t dst = sb + slot * STAGE_B + TILE_A + (uint32_t)brow * SMSTRIDE_B + bch;
            asm volatile("cp.async.cg.shared.global [%0], [%1], 16;"
                         :: "r"(dst), "l"(src));
        }
    };

    const int wm = wid & 3;
    const int wn = wid >> 2;
    const int g  = lane >> 2;
    const int t  = lane & 3;
    const int lane7 = lane & 7;
    const int quad  = lane >> 3;

    const int a_moff = (quad & 1) * 8;
    const int a_koff = (quad >> 1) * 16;
    const int b_noff = (quad >> 1) * 8;
    const int b_koff = (quad & 1) * 16;

    float acc[2][8][4];
#pragma unroll
    for (int i = 0; i < 2; i++)
#pragma unroll
        for (int j = 0; j < 8; j++)
#pragma unroll
            for (int r = 0; r < 4; r++) acc[i][j][r] = 0.f;

#pragma unroll
    for (int s = 0; s < GNS - 1; s++) {
        load_stage(s, s);
        asm volatile("cp.async.commit_group;" ::: "memory");
    }

    int slot = 0;
    for (int kt = 0; kt < KT; kt++) {
        asm volatile("cp.async.wait_group %0;" :: "n"(GNS - 2) : "memory");
        __syncthreads();   // publishes stage kt AND proves kt-1 consumed

        if (kt + GNS - 1 < KT) load_stage((kt + GNS - 1) % GNS, kt + GNS - 1);
        asm volatile("cp.async.commit_group;" ::: "memory");

        const uint32_t sA = sb + slot * STAGE_B;
        const uint32_t sB = sA + TILE_A;

#pragma unroll
        for (int kh = 0; kh < 2; kh++) {
            const int kb = kh * 32;
            uint32_t ah[2][4];
#pragma unroll
            for (int i = 0; i < 2; i++) {
                uint32_t ra = (uint32_t)(wm * 32 + i * 16 + a_moff + lane7) * SMSTRIDE_B
                              + kb + a_koff;
                LDSM_X4(ah[i][0], ah[i][1], ah[i][2], ah[i][3], sA + ra);
            }
#pragma unroll
            for (int jp = 0; jp < 4; jp++) {
                uint32_t rb = (uint32_t)(wn * 64 + jp * 16 + b_noff + lane7) * SMSTRIDE_B
                              + kb + b_koff;
                uint32_t bfr[4];
                LDSM_X4(bfr[0], bfr[1], bfr[2], bfr[3], sB + rb);
#pragma unroll
                for (int jj = 0; jj < 2; jj++) {
                    int j = jp * 2 + jj;
#pragma unroll
                    for (int i = 0; i < 2; i++)
                        mma16816(acc[i][j], ah[i], &bfr[jj * 2]);
                }
            }
        }
        slot = (slot + 1 == GNS) ? 0 : slot + 1;
    }

#pragma unroll
    for (int i = 0; i < 2; i++) {
        int gr0 = row0 + wm * 32 + i * 16 + g;
#pragma unroll
        for (int j = 0; j < 8; j++) {
            int gc = col0 + wn * 64 + j * 8 + t * 2;
            float b0 = bias[gc], b1 = bias[gc + 1];
            if (gr0 < M)
                store2(&C[(size_t)gr0 * NT + gc], acc[i][j][0] + b0, acc[i][j][1] + b1);
            if (gr0 + 8 < M)
                store2(&C[(size_t)(gr0 + 8) * NT + gc], acc[i][j][2] + b0, acc[i][j][3] + b1);
        }
    }
}

// ===================== conversion / prologue kernels =====================
__global__ __launch_bounds__(256)
void cvt_x(const float* __restrict__ x)
{
    int i = blockIdx.x * blockDim.x + threadIdx.x;
    if (i < NN * IN_DIM) g_xh[i] = __float2half_rn(x[i]);
}

__global__ __launch_bounds__(256)
void transpose_h(const float* __restrict__ W, __half* __restrict__ wt, int K, int N)
{
    __shared__ float tbuf[32][33];
    int k0 = blockIdx.x * 32, n0 = blockIdx.y * 32;
    int tx = threadIdx.x, ty = threadIdx.y;
#pragma unroll
    for (int i = ty; i < 32; i += 8) {
        int n = n0 + tx;
        tbuf[i][tx] = (n < N) ? W[(size_t)(k0 + i) * N + n] : 0.f;
    }
    __syncthreads();
#pragma unroll
    for (int i = ty; i < 32; i += 8)
        wt[(size_t)(n0 + i) * K + (k0 + tx)] = __float2half_rn(tbuf[tx][i]);
}

__global__ __launch_bounds__(256)
void pack_bias(const float* __restrict__ bq, const float* __restrict__ bk,
               const float* __restrict__ bv, const float* __restrict__ bs,
               const float* __restrict__ bl, const float* __restrict__ br)
{
    int i = blockIdx.x * blockDim.x + threadIdx.x;
    if (i < N1TOT) {
        int seg = i >> 11, c = i & 2047;
        g_bias1[i] = (seg == 0) ? bq[c] : (seg == 1) ? bk[c] : (seg == 2) ? bv[c] : bs[c];
    }
    if (i < N2TOT) {
        int seg = i / D2PAD, c = i % D2PAD;
        g_bias2[i] = (c < D2) ? ((seg == 0) ? bl[c] : br[c]) : 0.f;
    }
}

// ===================== graph prologue: edges + CSR =====================
__global__ void zero_state()
{
    int i = blockIdx.x * blockDim.x + threadIdx.x;
    if (i < NN) { g_cnt[i] = 0; g_fill[i] = 0; }
}

__global__ __launch_bounds__(256)
void cvt_edges(const void* __restrict__ ei_raw)
{
    const long long* e64 = (const long long*)ei_raw;
    const int*       e32 = (const int*)ei_raw;
    bool is64 = true;
#pragma unroll
    for (int j = 0; j < 16; j++) {
        long long v = e64[j * 1000];
        if (v < 0 || v >= NN) { is64 = false; break; }
    }
    int e = blockIdx.x * blockDim.x + threadIdx.x;
    if (e >= EE) return;
    long long s, d;
    if (is64) { s = e64[2 * e]; d = e64[2 * e + 1]; }
    else      { s = e32[2 * e]; d = e32[2 * e + 1]; }
    if (s < 0) s = 0; if (s >= NN) s = NN - 1;
    if (d < 0) d = 0; if (d >= NN) d = NN - 1;
    g_src[e] = (int)s;
    g_dst[e] = (int)d;
    atomicAdd(&g_cnt[(int)d], 1);
}

__global__ __launch_bounds__(1024)
void scan_counts()
{
    __shared__ int sm[1024];
    const int tid = threadIdx.x;
    const int per = (NN + 1023) / 1024;     // 10
    const int start = tid * per;
    int sum = 0;
#pragma unroll
    for (int i = 0; i < per; i++)
        if (start + i < NN) sum += g_cnt[start + i];
    sm[tid] = sum;
    __syncthreads();
    for (int off = 1; off < 1024; off <<= 1) {
        int v = (tid >= off) ? sm[tid - off] : 0;
        __syncthreads();
        sm[tid] += v;
        __syncthreads();
    }
    int run = sm[tid] - sum;                // exclusive
#pragma unroll
    for (int i = 0; i < per; i++) {
        if (start + i < NN) {
            g_rowptr[start + i] = run;
            run += g_cnt[start + i];
        }
    }
    if (tid == 0) g_rowptr[NN] = EE;
}

__global__ __launch_bounds__(256)
void scatter_edges()
{
    int e = blockIdx.x * blockDim.x + threadIdx.x;
    if (e >= EE) return;
    int d = g_dst[e];
    int pos = g_rowptr[d] + atomicAdd(&g_fill[d], 1);
    g_csr_src[pos] = g_src[e];
}

// ===================== fused attention + aggregation, layer 1 =====================
__global__ __launch_bounds__(256)
void attn_agg1()
{
    const int d   = blockIdx.x;
    const int tid = threadIdx.x;
    const int wid = tid >> 5, lane = tid & 31;
    const int beg = g_rowptr[d], end = g_rowptr[d + 1];

    __shared__ __half s_q[D1];
    __shared__ float  s_den[H1];
    __shared__ float  s_inv[H1];
    __shared__ float  s_w[64][H1];
    __shared__ int    s_s[64];

    {
        const uint4* src = (const uint4*)&g_b1[(size_t)d * S1 + OFF_Q];
        ((uint4*)s_q)[tid] = src[tid];
    }
    if (tid < H1) s_den[tid] = 0.f;
    __syncthreads();

    // pass 1: 8 warps = 2 edge slots x 4 heads
    {
        const int head = wid & 3;
        const int eoff = wid >> 2;
        float den = 0.f;
        for (int i = beg + eoff; i < end; i += 2) {
            int s = g_csr_src[i];
            const __half* kp = &g_b1[(size_t)s * S1 + OFF_K + head * C1];
            const __half* qp = &s_q[head * C1];
            float acc = 0.f;
#pragma unroll
            for (int c = lane * 4; c < C1; c += 128) {
                float4 a = ld_half4(qp + c);
                float4 b = ld_half4(kp + c);
                acc += a.x * b.x + a.y * b.y + a.z * b.z + a.w * b.w;
            }
#pragma unroll
            for (int o = 16; o; o >>= 1) acc += __shfl_xor_sync(0xFFFFFFFFu, acc, o);
            if (lane == 0) {
                float ex = expf(acc * 0.04419417382415922f);   // / sqrt(512)
                g_ex1[i * H1 + head] = ex;
                den += ex;
            }
        }
        if (lane == 0) atomicAdd(&s_den[head], den);
    }
    __syncthreads();
    if (tid < H1) s_inv[tid] = 1.f / (s_den[tid] + 1e-16f);
    __syncthreads();

    // pass 2: aggregate v[src]
    float4 acc[2];
    acc[0] = make_float4(0.f, 0.f, 0.f, 0.f);
    acc[1] = make_float4(0.f, 0.f, 0.f, 0.f);

    for (int base = beg; base < end; base += 64) {
        int n = min(64, end - base);
        __syncthreads();
        if (tid < n) s_s[tid] = g_csr_src[base + tid];
        for (int idx = tid; idx < n * H1; idx += 256) {
            int ei = idx >> 2, h = idx & 3;
            s_w[ei][h] = g_ex1[(base + ei) * H1 + h] * s_inv[h];
        }
        __syncthreads();
        for (int i = 0; i < n; i++) {
            int s = s_s[i];
#pragma unroll
            for (int it = 0; it < 2; it++) {
                int c = tid * 4 + it * 1024;
                float w = s_w[i][c >> 9];
                float4 v = ld_half4(&g_b1[(size_t)s * S1 + OFF_V + c]);
                acc[it].x += v.x * w; acc[it].y += v.y * w;
                acc[it].z += v.z * w; acc[it].w += v.w * w;
            }
        }
    }

#pragma unroll
    for (int it = 0; it < 2; it++) {
        int c = tid * 4 + it * 1024;
        float4 sk = ld_half4(&g_b1[(size_t)d * S1 + OFF_H + c]);
        float e0 = sk.x + acc[it].x, e1 = sk.y + acc[it].y;
        float e2 = sk.z + acc[it].z, e3 = sk.w + acc[it].w;
        e0 = (e0 > 0.f) ? e0 : expm1f(e0);
        e1 = (e1 > 0.f) ? e1 : expm1f(e1);
        e2 = (e2 > 0.f) ? e2 : expm1f(e2);
        e3 = (e3 > 0.f) ? e3 : expm1f(e3);
        __half* hp = &g_hh[(size_t)d * D1 + c];
        *(__half2*)(hp)     = __floats2half2_rn(e0, e1);
        *(__half2*)(hp + 2) = __floats2half2_rn(e2, e3);
    }
}

// ===================== fused attention + aggregation, layer 2 =====================
// SINGLE PASS with deferred normalization:
//   out[c] = b_out[c] + (1/H2) * sum_h ( sum_e ex[e,h]*gl[s_e,h,c] ) / den[h]
// Each edge: stage gl[src] row in smem once; warp-per-head dot -> ex (smem);
// all threads accumulate 16 per-head partials from the SAME smem copy.
// gl gathered ONCE per edge (was twice); no g_ex2 global round trip.
__global__ __launch_bounds__(256)
void attn_agg2(const float* __restrict__ att,
               float* __restrict__ out, const float* __restrict__ b_out)
{
    const int d   = blockIdx.x;
    const int tid = threadIdx.x;
    const int wid = tid >> 5, lane = tid & 31;
    const int beg = g_rowptr[d], end = g_rowptr[d + 1];

    __shared__ __half s_gr[D2];           // 7360 B
    __shared__ __half s_gl[D2];           // 7360 B (current edge's gl row)
    __shared__ float  s_att[H2 * C2];     // 14720 B
    __shared__ float  s_ex[H2];
    __shared__ float  s_den[H2];

    // load gr[d] and att
    {
        const __half* src = &g_b2[(size_t)d * S2 + D2PAD];
        for (int i = tid * 4; i < D2; i += 1024)
            *(uint2*)&s_gl[i] = *(const uint2*)&src[i];   // temp stage via s_gl? no:
    }
    // (re-do cleanly: gr into s_gr)
    {
        const __half* src = &g_b2[(size_t)d * S2 + D2PAD];
        for (int i = tid * 4; i < D2; i += 1024)
            *(uint2*)&s_gr[i] = *(const uint2*)&src[i];
        for (int i = tid; i < H2 * C2; i += 256)
            s_att[i] = att[i];
    }
    __syncthreads();

    const int c0 = tid, c1 = tid + 256;
    float acch[2][H2];
#pragma unroll
    for (int h = 0; h < H2; h++) { acch[0][h] = 0.f; acch[1][h] = 0.f; }
    float den_reg = 0.f;                  // valid on lane 0 of each warp (head = wid)

    // edges [beg-1, end): index beg-1 = self loop (src = d)
    for (int i = beg - 1; i < end; i++) {
        int s = (i < beg) ? d : g_csr_src[i];

        // stage gl[s] into smem (460 x 16B chunks)
        {
            const uint4* src = (const uint4*)&g_b2[(size_t)s * S2];
            for (int j = tid; j < D2 / 8; j += 256)       // 460 chunks
                ((uint4*)s_gl)[j] = src[j];
        }
        __syncthreads();

        // warp-per-head dot from smem
        {
            const int head = wid;
            const __half* glp = &s_gl[head * C2];
            const __half* grp = &s_gr[head * C2];
            const float*  ap  = &s_att[head * C2];
            float acc = 0.f;
            for (int c = lane; c < C2; c += 32) {
                float x = __half2float(glp[c]) + __half2float(grp[c]);
                x = (x > 0.f) ? x : 0.2f * x;
                acc += x * ap[c];
            }
#pragma unroll
            for (int o = 16; o; o >>= 1) acc += __shfl_xor_sync(0xFFFFFFFFu, acc, o);
            if (lane == 0) {
                float ex = expf(acc);
                s_ex[head] = ex;
                den_reg += ex;
            }
        }
        __syncthreads();

        // accumulate unnormalized numerators from the same smem copy
#pragma unroll
        for (int h = 0; h < H2; h++) {
            float ex = s_ex[h];
            acch[0][h] += ex * __half2float(s_gl[h * C2 + c0]);
            if (c1 < C2) acch[1][h] += ex * __half2float(s_gl[h * C2 + c1]);
        }
        __syncthreads();   // before next edge overwrites s_gl / s_ex
    }

    // publish per-head denominators (warp wid owns head wid)
    if (lane == 0) s_den[wid] = den_reg;
    __syncthreads();

    float o0 = 0.f, o1 = 0.f;
#pragma unroll
    for (int h = 0; h < H2; h++) {
        float inv = 1.f / (s_den[h] + 1e-16f);
        o0 += acch[0][h] * inv;
        o1 += acch[1][h] * inv;
    }
    if (c0 < C2) out[(size_t)d * C2 + c0] = b_out[c0] + o0 * (1.f / H2);
    if (c1 < C2) out[(size_t)d * C2 + c1] = b_out[c1] + o1 * (1.f / H2);
}

// ===================== host launcher =====================
extern "C" void kernel_launch(void* const* d_in, const int* in_sizes, int n_in,
                              void* d_out, int out_size)
{
    const float* x     = (const float*)d_in[0];
    const void*  ei    = d_in[1];
    const float* Wq    = (const float*)d_in[2];
    const float* bq    = (const float*)d_in[3];
    const float* Wk    = (const float*)d_in[4];
    const float* bk    = (const float*)d_in[5];
    const float* Wv    = (const float*)d_in[6];
    const float* bv    = (const float*)d_in[7];
    const float* Wskip = (const float*)d_in[8];
    const float* bskip = (const float*)d_in[9];
    const float* Wl    = (const float*)d_in[10];
    const float* bl    = (const float*)d_in[11];
    const float* Wr    = (const float*)d_in[12];
    const float* br    = (const float*)d_in[13];
    const float* att   = (const float*)d_in[14];
    const float* b_out = (const float*)d_in[15];
    float*       out   = (float*)d_out;

    float *pbias1, *pbias2;
    __half *pb1, *pb2;
    cudaGetSymbolAddress((void**)&pb1,    g_b1);
    cudaGetSymbolAddress((void**)&pb2,    g_b2);
    cudaGetSymbolAddress((void**)&pbias1, g_bias1);
    cudaGetSymbolAddress((void**)&pbias2, g_bias2);
    __half *pxh, *phh, *pw1, *pw2;
    cudaGetSymbolAddress((void**)&pxh, g_xh);
    cudaGetSymbolAddress((void**)&phh, g_hh);
    cudaGetSymbolAddress((void**)&pw1, g_wt1);
    cudaGetSymbolAddress((void**)&pw2, g_wt2);

    cudaFuncSetAttribute(gemm_mma, cudaFuncAttributeMaxDynamicSharedMemorySize, GEMM_SMEM);

    // state reset + edge ingestion + CSR build
    zero_state<<<(NN + 255) / 256, 256>>>();
    cvt_edges<<<(EE + 255) / 256, 256>>>(ei);
    scan_counts<<<1, 1024>>>();
    scatter_edges<<<(EE + 255) / 256, 256>>>();
    pack_bias<<<(N1TOT + 255) / 256, 256>>>(bq, bk, bv, bskip, bl, br);

    // operand conversions
    cvt_x<<<(NN * IN_DIM + 255) / 256, 256>>>(x);
    {
        dim3 blk(32, 8);
        dim3 t1(IN_DIM / 32, D1 / 32);
        size_t w1 = (size_t)D1 * IN_DIM;
        transpose_h<<<t1, blk>>>(Wq,    pw1 + 0 * w1, IN_DIM, D1);
        transpose_h<<<t1, blk>>>(Wk,    pw1 + 1 * w1, IN_DIM, D1);
        transpose_h<<<t1, blk>>>(Wv,    pw1 + 2 * w1, IN_DIM, D1);
        transpose_h<<<t1, blk>>>(Wskip, pw1 + 3 * w1, IN_DIM, D1);
        dim3 t2(D1 / 32, D2PAD / 32);
        size_t w2 = (size_t)D2PAD * D1;
        transpose_h<<<t2, blk>>>(Wl, pw2 + 0 * w2, D1, D2);
        transpose_h<<<t2, blk>>>(Wr, pw2 + 1 * w2, D1, D2);
    }

    // --- layer 1 fused GEMM (fp16 out), 128x256 tiles ---
    {
        dim3 g1(N1TOT / 256, (NN + 127) / 128);   // (32, 79)
        gemm_mma<<<g1, 512, GEMM_SMEM>>>(pxh, pw1, pbias1, pb1, NN, N1TOT, IN_DIM);
    }

    // --- layer 1 fused attention + aggregation ---
    attn_agg1<<<NN, 256>>>();

    // --- layer 2 fused GEMM (fp16 out), 128x256 tiles ---
    {
        dim3 g2(N2TOT / 256, (NN + 127) / 128);   // (29, 79)
        gemm_mma<<<g2, 512, GEMM_SMEM>>>(phh, pw2, pbias2, pb2, NN, N2TOT, D1);
    }

    // --- layer 2 fused attention + aggregation (single pass) ---
    attn_agg2<<<NN, 256>>>(att, out, b_out);
}

// round 17
// speedup vs baseline: 1.0147x; 1.0147x over previous
#include <cuda_runtime.h>
#include <cuda_bf16.h>
#include <cuda_fp16.h>
#include <math.h>
#include <stdint.h>

// ----- problem constants (fixed shapes) -----
#define NN     10000
#define EE     30000
#define IN_DIM 1024
#define H1     4
#define C1     512
#define D1     2048          // H1*C1
#define H2     8
#define C2     460
#define D2     3680          // H2*C2
#define D2PAD  3712          // 29*128
#define E2TOT  40000         // EE + NN (self loops)

#define S1     8192          // packed L1 output row stride: [q|k|v|skip]
#define OFF_Q  0
#define OFF_K  2048
#define OFF_V  4096
#define OFF_H  6144
#define S2     7424          // packed L2 output row stride: [gl(3712)|gr(3712)]
#define N1TOT  8192
#define N2TOT  7424

// ----- scratch (device globals; no allocations allowed) -----
__device__ __half g_b1[NN * S1];      // q|k|v|skip packed (fp16)
__device__ __half g_b2[NN * S2];      // gl|gr packed (fp16)
__device__ float  g_ex1[EE * H1];     // CSR-ordered exp(alpha), layer 1
__device__ int    g_src[EE];
__device__ int    g_dst[EE];
__device__ float  g_bias1[N1TOT];
__device__ float  g_bias2[N2TOT];

// CSR by dst (shared by both layers; layer-2 self loops handled inline)
__device__ int    g_cnt[NN];
__device__ int    g_fill[NN];
__device__ int    g_rowptr[NN + 1];
__device__ int    g_csr_src[EE];

// fp16 operands (A single fp16, weights single fp16 K-major [Ntot, K])
__device__ __half g_xh[NN * IN_DIM];
__device__ __half g_hh[NN * D1];
__device__ __half g_wt1[4 * D1 * IN_DIM];
__device__ __half g_wt2[2 * D2PAD * D1];

// ===================== GEMM (mma.sync fp16, 128x256 tile, 512 thr,
//                       ldmatrix, 5-stage, single barrier / K-step) =======
#define SMSTRIDE_B 80
#define TILE_A     (128 * SMSTRIDE_B)    // 10240
#define TILE_BB    (256 * SMSTRIDE_B)    // 20480
#define STAGE_B    (TILE_A + TILE_BB)    // 30720
#define GNS        5
#define GEMM_SMEM  (GNS * STAGE_B)       // 153600 -> 1 CTA/SM, 16 warps

__device__ __forceinline__ uint32_t smem_u32(const void* p) {
    uint32_t a;
    asm("{ .reg .u64 t; cvta.to.shared.u64 t, %1; cvt.u32.u64 %0, t; }" : "=r"(a) : "l"(p));
    return a;
}

__device__ __forceinline__ void mma16816(float* c, const uint32_t* a, const uint32_t* b)
{
    asm volatile(
        "mma.sync.aligned.m16n8k16.row.col.f32.f16.f16.f32 "
        "{%0,%1,%2,%3}, {%4,%5,%6,%7}, {%8,%9}, {%0,%1,%2,%3};"
        : "+f"(c[0]), "+f"(c[1]), "+f"(c[2]), "+f"(c[3])
        : "r"(a[0]), "r"(a[1]), "r"(a[2]), "r"(a[3]), "r"(b[0]), "r"(b[1]));
}

#define LDSM_X4(r0, r1, r2, r3, addr) \
    asm volatile("ldmatrix.sync.aligned.m8n8.x4.shared.b16 {%0,%1,%2,%3}, [%4];" \
                 : "=r"(r0), "=r"(r1), "=r"(r2), "=r"(r3) : "r"(addr))

__device__ __forceinline__ void store2(__half* p, float a, float b)
{ *(__half2*)p = __floats2half2_rn(a, b); }

// load 4 consecutive halves -> float4 (generic: works on global or smem)
__device__ __forceinline__ float4 ld_half4(const __half* p)
{
    uint2 u = *(const uint2*)p;
    __half2 h0 = *(__half2*)&u.x, h1 = *(__half2*)&u.y;
    float2 a = __half22float2(h0), b = __half22float2(h1);
    return make_float4(a.x, a.y, b.x, b.y);
}

__global__ __launch_bounds__(512, 1)
void gemm_mma(const __half* __restrict__ A, const __half* __restrict__ B,
              const float* __restrict__ bias, __half* __restrict__ C,
              int M, int NT, int K)
{
    extern __shared__ char smem[];
    const uint32_t sb = smem_u32(smem);
    const int tid  = threadIdx.x;
    const int wid  = tid >> 5, lane = tid & 31;
    const int row0 = blockIdx.y * 128;
    const int col0 = blockIdx.x * 256;
    const int KT   = K >> 5;

    const int aRow = tid >> 2, aChunk = (tid & 3) * 16;

    auto load_stage = [&](int slot, int kt) {
        {
            int grow = row0 + aRow;
            int sz = 16;
            if (grow >= M) { grow = M - 1; sz = 0; }
            const char* src = (const char*)A + (size_t)grow * ((size_t)K * 2)
                              + (size_t)kt * 64 + aChunk;
            uint32_t dst = sb + slot * STAGE_B + (uint32_t)aRow * SMSTRIDE_B + aChunk;
            asm volatile("cp.async.cg.shared.global [%0], [%1], 16, %2;"
                         :: "r"(dst), "l"(src), "r"(sz));
        }
#pragma unroll
        for (int r = 0; r < 2; r++) {
            int idx  = tid + r * 512;
            int brow = idx >> 2, bch = (idx & 3) * 16;
            const char* src = (const char*)B + (size_t)(col0 + brow) * ((size_t)K * 2)
                              + (size_t)kt * 64 + bch;
            uint32_t dst = sb + slot * STAGE_B + TILE_A + (uint32_t)brow * SMSTRIDE_B + bch;
            asm volatile("cp.async.cg.shared.global [%0], [%1], 16;"
                         :: "r"(dst), "l"(src));
        }
    };

    const int wm = wid & 3;
    const int wn = wid >> 2;
    const int g  = lane >> 2;
    const int t  = lane & 3;
    const int lane7 = lane & 7;
    const int quad  = lane >> 3;

    const int a_moff = (quad & 1) * 8;
    const int a_koff = (quad >> 1) * 16;
    const int b_noff = (quad >> 1) * 8;
    const int b_koff = (quad & 1) * 16;

    float acc[2][8][4];
#pragma unroll
    for (int i = 0; i < 2; i++)
#pragma unroll
        for (int j = 0; j < 8; j++)
#pragma unroll
            for (int r = 0; r < 4; r++) acc[i][j][r] = 0.f;

#pragma unroll
    for (int s = 0; s < GNS - 1; s++) {
        load_stage(s, s);
        asm volatile("cp.async.commit_group;" ::: "memory");
    }

    int slot = 0;
    for (int kt = 0; kt < KT; kt++) {
        asm volatile("cp.async.wait_group %0;" :: "n"(GNS - 2) : "memory");
        __syncthreads();   // publishes stage kt AND proves kt-1 consumed

        if (kt + GNS - 1 < KT) load_stage((kt + GNS - 1) % GNS, kt + GNS - 1);
        asm volatile("cp.async.commit_group;" ::: "memory");

        const uint32_t sA = sb + slot * STAGE_B;
        const uint32_t sB = sA + TILE_A;

#pragma unroll
        for (int kh = 0; kh < 2; kh++) {
            const int kb = kh * 32;
            uint32_t ah[2][4];
#pragma unroll
            for (int i = 0; i < 2; i++) {
                uint32_t ra = (uint32_t)(wm * 32 + i * 16 + a_moff + lane7) * SMSTRIDE_B
                              + kb + a_koff;
                LDSM_X4(ah[i][0], ah[i][1], ah[i][2], ah[i][3], sA + ra);
            }
#pragma unroll
            for (int jp = 0; jp < 4; jp++) {
                uint32_t rb = (uint32_t)(wn * 64 + jp * 16 + b_noff + lane7) * SMSTRIDE_B
                              + kb + b_koff;
                uint32_t bfr[4];
                LDSM_X4(bfr[0], bfr[1], bfr[2], bfr[3], sB + rb);
#pragma unroll
                for (int jj = 0; jj < 2; jj++) {
                    int j = jp * 2 + jj;
#pragma unroll
                    for (int i = 0; i < 2; i++)
                        mma16816(acc[i][j], ah[i], &bfr[jj * 2]);
                }
            }
        }
        slot = (slot + 1 == GNS) ? 0 : slot + 1;
    }

#pragma unroll
    for (int i = 0; i < 2; i++) {
        int gr0 = row0 + wm * 32 + i * 16 + g;
#pragma unroll
        for (int j = 0; j < 8; j++) {
            int gc = col0 + wn * 64 + j * 8 + t * 2;
            float b0 = bias[gc], b1 = bias[gc + 1];
            if (gr0 < M)
                store2(&C[(size_t)gr0 * NT + gc], acc[i][j][0] + b0, acc[i][j][1] + b1);
            if (gr0 + 8 < M)
                store2(&C[(size_t)(gr0 + 8) * NT + gc], acc[i][j][2] + b0, acc[i][j][3] + b1);
        }
    }
}

// ===================== conversion / prologue kernels =====================
__global__ __launch_bounds__(256)
void cvt_x(const float* __restrict__ x)
{
    int i = blockIdx.x * blockDim.x + threadIdx.x;
    if (i < NN * IN_DIM) g_xh[i] = __float2half_rn(x[i]);
}

__global__ __launch_bounds__(256)
void transpose_h(const float* __restrict__ W, __half* __restrict__ wt, int K, int N)
{
    __shared__ float tbuf[32][33];
    int k0 = blockIdx.x * 32, n0 = blockIdx.y * 32;
    int tx = threadIdx.x, ty = threadIdx.y;
#pragma unroll
    for (int i = ty; i < 32; i += 8) {
        int n = n0 + tx;
        tbuf[i][tx] = (n < N) ? W[(size_t)(k0 + i) * N + n] : 0.f;
    }
    __syncthreads();
#pragma unroll
    for (int i = ty; i < 32; i += 8)
        wt[(size_t)(n0 + i) * K + (k0 + tx)] = __float2half_rn(tbuf[tx][i]);
}

__global__ __launch_bounds__(256)
void pack_bias(const float* __restrict__ bq, const float* __restrict__ bk,
               const float* __restrict__ bv, const float* __restrict__ bs,
               const float* __restrict__ bl, const float* __restrict__ br)
{
    int i = blockIdx.x * blockDim.x + threadIdx.x;
    if (i < N1TOT) {
        int seg = i >> 11, c = i & 2047;
        g_bias1[i] = (seg == 0) ? bq[c] : (seg == 1) ? bk[c] : (seg == 2) ? bv[c] : bs[c];
    }
    if (i < N2TOT) {
        int seg = i / D2PAD, c = i % D2PAD;
        g_bias2[i] = (c < D2) ? ((seg == 0) ? bl[c] : br[c]) : 0.f;
    }
}

// ===================== graph prologue: edges + CSR =====================
__global__ void zero_state()
{
    int i = blockIdx.x * blockDim.x + threadIdx.x;
    if (i < NN) { g_cnt[i] = 0; g_fill[i] = 0; }
}

__global__ __launch_bounds__(256)
void cvt_edges(const void* __restrict__ ei_raw)
{
    const long long* e64 = (const long long*)ei_raw;
    const int*       e32 = (const int*)ei_raw;
    bool is64 = true;
#pragma unroll
    for (int j = 0; j < 16; j++) {
        long long v = e64[j * 1000];
        if (v < 0 || v >= NN) { is64 = false; break; }
    }
    int e = blockIdx.x * blockDim.x + threadIdx.x;
    if (e >= EE) return;
    long long s, d;
    if (is64) { s = e64[2 * e]; d = e64[2 * e + 1]; }
    else      { s = e32[2 * e]; d = e32[2 * e + 1]; }
    if (s < 0) s = 0; if (s >= NN) s = NN - 1;
    if (d < 0) d = 0; if (d >= NN) d = NN - 1;
    g_src[e] = (int)s;
    g_dst[e] = (int)d;
    atomicAdd(&g_cnt[(int)d], 1);
}

__global__ __launch_bounds__(1024)
void scan_counts()
{
    __shared__ int sm[1024];
    const int tid = threadIdx.x;
    const int per = (NN + 1023) / 1024;     // 10
    const int start = tid * per;
    int sum = 0;
#pragma unroll
    for (int i = 0; i < per; i++)
        if (start + i < NN) sum += g_cnt[start + i];
    sm[tid] = sum;
    __syncthreads();
    for (int off = 1; off < 1024; off <<= 1) {
        int v = (tid >= off) ? sm[tid - off] : 0;
        __syncthreads();
        sm[tid] += v;
        __syncthreads();
    }
    int run = sm[tid] - sum;                // exclusive
#pragma unroll
    for (int i = 0; i < per; i++) {
        if (start + i < NN) {
            g_rowptr[start + i] = run;
            run += g_cnt[start + i];
        }
    }
    if (tid == 0) g_rowptr[NN] = EE;
}

__global__ __launch_bounds__(256)
void scatter_edges()
{
    int e = blockIdx.x * blockDim.x + threadIdx.x;
    if (e >= EE) return;
    int d = g_dst[e];
    int pos = g_rowptr[d] + atomicAdd(&g_fill[d], 1);
    g_csr_src[pos] = g_src[e];
}

// ===================== fused attention + aggregation, layer 1 =====================
__global__ __launch_bounds__(256)
void attn_agg1()
{
    const int d   = blockIdx.x;
    const int tid = threadIdx.x;
    const int wid = tid >> 5, lane = tid & 31;
    const int beg = g_rowptr[d], end = g_rowptr[d + 1];

    __shared__ __half s_q[D1];
    __shared__ float  s_den[H1];
    __shared__ float  s_inv[H1];
    __shared__ float  s_w[64][H1];
    __shared__ int    s_s[64];

    {
        const uint4* src = (const uint4*)&g_b1[(size_t)d * S1 + OFF_Q];
        ((uint4*)s_q)[tid] = src[tid];
    }
    if (tid < H1) s_den[tid] = 0.f;
    __syncthreads();

    // pass 1: 8 warps = 2 edge slots x 4 heads
    {
        const int head = wid & 3;
        const int eoff = wid >> 2;
        float den = 0.f;
        for (int i = beg + eoff; i < end; i += 2) {
            int s = g_csr_src[i];
            const __half* kp = &g_b1[(size_t)s * S1 + OFF_K + head * C1];
            const __half* qp = &s_q[head * C1];
            float acc = 0.f;
#pragma unroll
            for (int c = lane * 4; c < C1; c += 128) {
                float4 a = ld_half4(qp + c);
                float4 b = ld_half4(kp + c);
                acc += a.x * b.x + a.y * b.y + a.z * b.z + a.w * b.w;
            }
#pragma unroll
            for (int o = 16; o; o >>= 1) acc += __shfl_xor_sync(0xFFFFFFFFu, acc, o);
            if (lane == 0) {
                float ex = expf(acc * 0.04419417382415922f);   // / sqrt(512)
                g_ex1[i * H1 + head] = ex;
                den += ex;
            }
        }
        if (lane == 0) atomicAdd(&s_den[head], den);
    }
    __syncthreads();
    if (tid < H1) s_inv[tid] = 1.f / (s_den[tid] + 1e-16f);
    __syncthreads();

    // pass 2: aggregate v[src]
    float4 acc[2];
    acc[0] = make_float4(0.f, 0.f, 0.f, 0.f);
    acc[1] = make_float4(0.f, 0.f, 0.f, 0.f);

    for (int base = beg; base < end; base += 64) {
        int n = min(64, end - base);
        __syncthreads();
        if (tid < n) s_s[tid] = g_csr_src[base + tid];
        for (int idx = tid; idx < n * H1; idx += 256) {
            int ei = idx >> 2, h = idx & 3;
            s_w[ei][h] = g_ex1[(base + ei) * H1 + h] * s_inv[h];
        }
        __syncthreads();
        for (int i = 0; i < n; i++) {
            int s = s_s[i];
#pragma unroll
            for (int it = 0; it < 2; it++) {
                int c = tid * 4 + it * 1024;
                float w = s_w[i][c >> 9];
                float4 v = ld_half4(&g_b1[(size_t)s * S1 + OFF_V + c]);
                acc[it].x += v.x * w; acc[it].y += v.y * w;
                acc[it].z += v.z * w; acc[it].w += v.w * w;
            }
        }
    }

#pragma unroll
    for (int it = 0; it < 2; it++) {
        int c = tid * 4 + it * 1024;
        float4 sk = ld_half4(&g_b1[(size_t)d * S1 + OFF_H + c]);
        float e0 = sk.x + acc[it].x, e1 = sk.y + acc[it].y;
        float e2 = sk.z + acc[it].z, e3 = sk.w + acc[it].w;
        e0 = (e0 > 0.f) ? e0 : expm1f(e0);
        e1 = (e1 > 0.f) ? e1 : expm1f(e1);
        e2 = (e2 > 0.f) ? e2 : expm1f(e2);
        e3 = (e3 > 0.f) ? e3 : expm1f(e3);
        __half* hp = &g_hh[(size_t)d * D1 + c];
        *(__half2*)(hp)     = __floats2half2_rn(e0, e1);
        *(__half2*)(hp + 2) = __floats2half2_rn(e2, e3);
    }
}

// ===================== fused attention + aggregation, layer 2 =====================
// Single pass, deferred normalization, DOUBLE-BUFFERED cp.async gl staging:
// edge i+1's gl row streams into s_gl[buf^1] while edge i is computed from
// s_gl[buf]. gl gathered once per edge; no global ex arrays.
#define GL_CHUNKS (D2 / 8)        // 460 x 16B
__global__ __launch_bounds__(256)
void attn_agg2(const float* __restrict__ att,
               float* __restrict__ out, const float* __restrict__ b_out)
{
    const int d   = blockIdx.x;
    const int tid = threadIdx.x;
    const int wid = tid >> 5, lane = tid & 31;
    const int beg = g_rowptr[d], end = g_rowptr[d + 1];

    __shared__ __half s_gr[D2];           // 7360 B
    __shared__ __half s_gl[2][D2];        // 14720 B
    __shared__ float  s_att[H2 * C2];     // 14720 B
    __shared__ float  s_ex[H2];
    __shared__ float  s_den[H2];

    const uint32_t gl_base = smem_u32(&s_gl[0][0]);

    auto load_gl = [&](int buf, int s) {
        const char* src = (const char*)&g_b2[(size_t)s * S2];
        uint32_t dst = gl_base + (uint32_t)buf * (D2 * 2);
        for (int j = tid; j < GL_CHUNKS; j += 256)
            asm volatile("cp.async.cg.shared.global [%0], [%1], 16;"
                         :: "r"(dst + j * 16), "l"(src + j * 16));
    };

    // prologue: start self-loop gl load (src = d), load gr[d] + att
    load_gl(0, d);
    asm volatile("cp.async.commit_group;" ::: "memory");
    {
        const __half* src = &g_b2[(size_t)d * S2 + D2PAD];
        for (int i = tid * 4; i < D2; i += 1024)
            *(uint2*)&s_gr[i] = *(const uint2*)&src[i];
        for (int i = tid; i < H2 * C2; i += 256)
            s_att[i] = att[i];
    }

    const int c0 = tid, c1 = tid + 256;
    float acch[2][H2];
#pragma unroll
    for (int h = 0; h < H2; h++) { acch[0][h] = 0.f; acch[1][h] = 0.f; }
    float den_reg = 0.f;                  // lane 0 of warp `wid` owns head wid

    // iterations: idx 0 = self loop, idx 1.. = CSR edges
    const int n_it = 1 + (end - beg);
    for (int idx = 0; idx < n_it; idx++) {
        const int buf = idx & 1;

        // issue next edge's gl load into buf^1 (safe: prev iter's trailing
        // barrier proved all threads finished reading buf^1)
        if (idx + 1 < n_it) load_gl(buf ^ 1, g_csr_src[beg + idx]);
        asm volatile("cp.async.commit_group;" ::: "memory");
        // complete all but the newest group -> current buf's data arrived
        asm volatile("cp.async.wait_group 1;" ::: "memory");
        __syncthreads();                   // cross-thread visibility of buf

        // warp-per-head dot from smem
        {
            const int head = wid;
            const __half* glp = &s_gl[buf][head * C2];
            const __half* grp = &s_gr[head * C2];
            const float*  ap  = &s_att[head * C2];
            float acc = 0.f;
            for (int c = lane; c < C2; c += 32) {
                float x = __half2float(glp[c]) + __half2float(grp[c]);
                x = (x > 0.f) ? x : 0.2f * x;
                acc += x * ap[c];
            }
#pragma unroll
            for (int o = 16; o; o >>= 1) acc += __shfl_xor_sync(0xFFFFFFFFu, acc, o);
            if (lane == 0) {
                float ex = expf(acc);
                s_ex[head] = ex;
                den_reg += ex;
            }
        }
        __syncthreads();                   // s_ex visible

        // accumulate unnormalized numerators from the same smem copy
#pragma unroll
        for (int h = 0; h < H2; h++) {
            float ex = s_ex[h];
            acch[0][h] += ex * __half2float(s_gl[buf][h * C2 + c0]);
            if (c1 < C2) acch[1][h] += ex * __half2float(s_gl[buf][h * C2 + c1]);
        }
        __syncthreads();                   // buf fully consumed before reuse
    }

    if (lane == 0) s_den[wid] = den_reg;   // warp wid owns head wid
    __syncthreads();

    float o0 = 0.f, o1 = 0.f;
#pragma unroll
    for (int h = 0; h < H2; h++) {
        float inv = 1.f / (s_den[h] + 1e-16f);
        o0 += acch[0][h] * inv;
        o1 += acch[1][h] * inv;
    }
    if (c0 < C2) out[(size_t)d * C2 + c0] = b_out[c0] + o0 * (1.f / H2);
    if (c1 < C2) out[(size_t)d * C2 + c1] = b_out[c1] + o1 * (1.f / H2);
}

// ===================== host launcher =====================
extern "C" void kernel_launch(void* const* d_in, const int* in_sizes, int n_in,
                              void* d_out, int out_size)
{
    const float* x     = (const float*)d_in[0];
    const void*  ei    = d_in[1];
    const float* Wq    = (const float*)d_in[2];
    const float* bq    = (const float*)d_in[3];
    const float* Wk    = (const float*)d_in[4];
    const float* bk    = (const float*)d_in[5];
    const float* Wv    = (const float*)d_in[6];
    const float* bv    = (const float*)d_in[7];
    const float* Wskip = (const float*)d_in[8];
    const float* bskip = (const float*)d_in[9];
    const float* Wl    = (const float*)d_in[10];
    const float* bl    = (const float*)d_in[11];
    const float* Wr    = (const float*)d_in[12];
    const float* br    = (const float*)d_in[13];
    const float* att   = (const float*)d_in[14];
    const float* b_out = (const float*)d_in[15];
    float*       out   = (float*)d_out;

    float *pbias1, *pbias2;
    __half *pb1, *pb2;
    cudaGetSymbolAddress((void**)&pb1,    g_b1);
    cudaGetSymbolAddress((void**)&pb2,    g_b2);
    cudaGetSymbolAddress((void**)&pbias1, g_bias1);
    cudaGetSymbolAddress((void**)&pbias2, g_bias2);
    __half *pxh, *phh, *pw1, *pw2;
    cudaGetSymbolAddress((void**)&pxh, g_xh);
    cudaGetSymbolAddress((void**)&phh, g_hh);
    cudaGetSymbolAddress((void**)&pw1, g_wt1);
    cudaGetSymbolAddress((void**)&pw2, g_wt2);

    cudaFuncSetAttribute(gemm_mma, cudaFuncAttributeMaxDynamicSharedMemorySize, GEMM_SMEM);

    // state reset + edge ingestion + CSR build
    zero_state<<<(NN + 255) / 256, 256>>>();
    cvt_edges<<<(EE + 255) / 256, 256>>>(ei);
    scan_counts<<<1, 1024>>>();
    scatter_edges<<<(EE + 255) / 256, 256>>>();
    pack_bias<<<(N1TOT + 255) / 256, 256>>>(bq, bk, bv, bskip, bl, br);

    // operand conversions
    cvt_x<<<(NN * IN_DIM + 255) / 256, 256>>>(x);
    {
        dim3 blk(32, 8);
        dim3 t1(IN_DIM / 32, D1 / 32);
        size_t w1 = (size_t)D1 * IN_DIM;
        transpose_h<<<t1, blk>>>(Wq,    pw1 + 0 * w1, IN_DIM, D1);
        transpose_h<<<t1, blk>>>(Wk,    pw1 + 1 * w1, IN_DIM, D1);
        transpose_h<<<t1, blk>>>(Wv,    pw1 + 2 * w1, IN_DIM, D1);
        transpose_h<<<t1, blk>>>(Wskip, pw1 + 3 * w1, IN_DIM, D1);
        dim3 t2(D1 / 32, D2PAD / 32);
        size_t w2 = (size_t)D2PAD * D1;
        transpose_h<<<t2, blk>>>(Wl, pw2 + 0 * w2, D1, D2);
        transpose_h<<<t2, blk>>>(Wr, pw2 + 1 * w2, D1, D2);
    }

    // --- layer 1 fused GEMM (fp16 out), 128x256 tiles ---
    {
        dim3 g1(N1TOT / 256, (NN + 127) / 128);   // (32, 79)
        gemm_mma<<<g1, 512, GEMM_SMEM>>>(pxh, pw1, pbias1, pb1, NN, N1TOT, IN_DIM);
    }

    // --- layer 1 fused attention + aggregation ---
    attn_agg1<<<NN, 256>>>();

    // --- layer 2 fused GEMM (fp16 out), 128x256 tiles ---
    {
        dim3 g2(N2TOT / 256, (NN + 127) / 128);   // (29, 79)
        gemm_mma<<<g2, 512, GEMM_SMEM>>>(phh, pw2, pbias2, pb2, NN, N2TOT, D1);
    }

    // --- layer 2 fused attention + aggregation (single pass, dbuf) ---
    attn_agg2<<<NN, 256>>>(att, out, b_out);
}